// round 2
// baseline (speedup 1.0000x reference)
#include <cuda_runtime.h>
#include <cuda_bf16.h>
#include <math.h>

#define NNODES 50000
#define NEDGES 800000
#define IN_DIM 128
#define HID 96
#define PROJ 64
#define BN_EPS 1e-5f

// ---------------- scratch (device globals; no allocation allowed) ----------
__device__ __align__(16) float g_xws[NNODES * HID];   // row-prescaled x@W
__device__ __align__(16) float g_agg[NNODES * HID];   // scatter accumulator
__device__ __align__(16) float g_h[NNODES * HID];     // pre-BN activations
__device__ float g_deg[NNODES];
__device__ float g_dinv[NNODES];
__device__ float g_sum[HID];
__device__ float g_sumsq[HID];
__device__ float g_a[HID];   // BN affine scale
__device__ float g_c[HID];   // BN affine shift
__device__ int   g_is64;     // edge_index dtype flag (1 = int64, 0 = int32)

// ---------------- dtype detection ----------------
// The reference builds edge_index with dtype=jnp.int64 but JAX x64 is off,
// so the actual buffer may be int32. Detect by range-checking the int64
// interpretation: true-int32 data merges adjacent indices -> huge values.
__global__ void detect_dtype_k(const void* __restrict__ ei) {
    __shared__ int bad;
    if (threadIdx.x == 0) bad = 0;
    __syncthreads();
    const long long* p = (const long long*)ei;
    for (int i = threadIdx.x; i < 4096; i += blockDim.x) {
        long long v = p[i];
        if (v < 0 || v >= NNODES) bad = 1;
    }
    __syncthreads();
    if (threadIdx.x == 0) g_is64 = bad ? 0 : 1;
}

__device__ __forceinline__ int edge_at(const void* ei, long pos) {
    if (g_is64) return (int)((const long long*)ei)[pos];
    return ((const int*)ei)[pos];
}

// ---------------- degree / dinv ----------------
__global__ void deg_init_k() {
    int i = blockIdx.x * blockDim.x + threadIdx.x;
    if (i < NNODES) g_deg[i] = 1.0f;   // self-loop
}

__global__ void deg_scatter_k(const void* __restrict__ ei) {
    int e = blockIdx.x * blockDim.x + threadIdx.x;
    if (e < NEDGES) {
        int dst = edge_at(ei, (long)NEDGES + e);
        atomicAdd(&g_deg[dst], 1.0f);
    }
}

__global__ void dinv_k() {
    int i = blockIdx.x * blockDim.x + threadIdx.x;
    if (i < NNODES) g_dinv[i] = rsqrtf(g_deg[i]);
}

// ---------------- zeroing ----------------
__global__ void zero_agg_stats_k() {
    int i = blockIdx.x * blockDim.x + threadIdx.x;
    long total = (long)NNODES * HID;
    if (i < total) g_agg[i] = 0.0f;
    if (i < HID) { g_sum[i] = 0.0f; g_sumsq[i] = 0.0f; }
}

__global__ void zero_stats_k() {
    int i = threadIdx.x;
    if (i < HID) { g_sum[i] = 0.0f; g_sumsq[i] = 0.0f; }
}

// ---------------- GEMM: C[M,96] = f(A[M,K]) @ B[K,96] (+bias) (*rowscale) ---
// f(v) = relu(ta[k]*v + tc[k]) when ta != nullptr (previous layer's BN+ReLU)
#define BM 64
#define BN 96
#define BK 32
__global__ void __launch_bounds__(256) gemm_k(
    const float* __restrict__ A, const float* __restrict__ B,
    const float* __restrict__ bias, float* __restrict__ C,
    int M, int K,
    const float* __restrict__ ta, const float* __restrict__ tc,
    const float* __restrict__ rowscale)
{
    __shared__ float As[BM][BK];
    __shared__ float Bs[BK][BN];

    int m0 = blockIdx.x * BM;
    int tid = threadIdx.x;
    int r = tid >> 4;      // 0..15
    int c = tid & 15;      // 0..15

    float acc[4][6];
#pragma unroll
    for (int i = 0; i < 4; i++)
#pragma unroll
        for (int j = 0; j < 6; j++) acc[i][j] = 0.0f;

    for (int k0 = 0; k0 < K; k0 += BK) {
        // load A tile (64x32), coalesced along k
#pragma unroll
        for (int l = 0; l < 8; l++) {
            int idx = tid + l * 256;
            int mr = idx >> 5;
            int kc = idx & 31;
            int m = m0 + mr;
            int kk = k0 + kc;
            float v = 0.0f;
            if (m < M) {
                v = A[(long)m * K + kk];
                if (ta) v = fmaxf(fmaf(ta[kk], v, tc[kk]), 0.0f);
            }
            As[mr][kc] = v;
        }
        // load B tile (32x96), coalesced along n
#pragma unroll
        for (int l = 0; l < 12; l++) {
            int idx = tid + l * 256;
            int kr = idx / 96;
            int nc = idx % 96;
            Bs[kr][nc] = B[(long)(k0 + kr) * BN + nc];
        }
        __syncthreads();

#pragma unroll
        for (int k = 0; k < BK; k++) {
            float av[4], bv[6];
#pragma unroll
            for (int i = 0; i < 4; i++) av[i] = As[r + 16 * i][k];
#pragma unroll
            for (int j = 0; j < 6; j++) bv[j] = Bs[k][c + 16 * j];
#pragma unroll
            for (int i = 0; i < 4; i++)
#pragma unroll
                for (int j = 0; j < 6; j++)
                    acc[i][j] = fmaf(av[i], bv[j], acc[i][j]);
        }
        __syncthreads();
    }

#pragma unroll
    for (int i = 0; i < 4; i++) {
        int m = m0 + r + 16 * i;
        if (m < M) {
            float rs = rowscale ? rowscale[m] : 1.0f;
#pragma unroll
            for (int j = 0; j < 6; j++) {
                int n = c + 16 * j;
                float v = acc[i][j];
                if (bias) v += bias[n];
                C[(long)m * BN + n] = v * rs;
            }
        }
    }
}

// ---------------- edge scatter: agg[dst] += xws[src] (96 floats as 24 f4) ---
__global__ void __launch_bounds__(256) scatter_k(const void* __restrict__ ei) {
    __shared__ int ssrc[32];
    __shared__ int sdst[32];
    int base = blockIdx.x * 32;
    int tid = threadIdx.x;
    if (tid < 32) {
        int e = base + tid;
        if (e < NEDGES) {
            ssrc[tid] = edge_at(ei, e);
            sdst[tid] = edge_at(ei, (long)NEDGES + e);
        } else {
            ssrc[tid] = -1;
        }
    }
    __syncthreads();

    const float4* xws4 = (const float4*)g_xws;
    float4* agg4 = (float4*)g_agg;

#pragma unroll
    for (int it = 0; it < 3; it++) {
        int item = it * 256 + tid;      // 0..767 = 32 edges * 24 float4
        int el = item / 24;
        int comp = item - el * 24;
        int s = ssrc[el];
        if (s >= 0) {
            float4 v = xws4[(long)s * 24 + comp];
            float4* p = &agg4[(long)sdst[el] * 24 + comp];
            asm volatile(
                "red.global.add.v4.f32 [%0], {%1, %2, %3, %4};"
                :: "l"(p), "f"(v.x), "f"(v.y), "f"(v.z), "f"(v.w)
                : "memory");
        }
    }
}

// ---------------- epilogue: h = dinv*(agg + xws) + b ; accumulate col stats -
__global__ void epilogue_k(const float* __restrict__ bias) {
    int c = threadIdx.x;   // 96 threads
    int rows_per = (NNODES + gridDim.x - 1) / gridDim.x;
    int r0 = blockIdx.x * rows_per;
    int r1 = min(r0 + rows_per, NNODES);
    float s = 0.0f, ss = 0.0f;
    for (int r = r0; r < r1; r++) {
        float di = g_dinv[r];
        long idx = (long)r * HID + c;
        float v = fmaf(di, g_agg[idx] + g_xws[idx], bias[c]);
        g_h[idx] = v;
        s += v;
        ss += v * v;
    }
    atomicAdd(&g_sum[c], s);
    atomicAdd(&g_sumsq[c], ss);
}

// ---------------- column stats of a [N,96] matrix ----------------
__global__ void stats_k(const float* __restrict__ X) {
    int c = threadIdx.x;
    int rows_per = (NNODES + gridDim.x - 1) / gridDim.x;
    int r0 = blockIdx.x * rows_per;
    int r1 = min(r0 + rows_per, NNODES);
    float s = 0.0f, ss = 0.0f;
    for (int r = r0; r < r1; r++) {
        float v = X[(long)r * HID + c];
        s += v;
        ss += v * v;
    }
    atomicAdd(&g_sum[c], s);
    atomicAdd(&g_sumsq[c], ss);
}

// ---------------- finalize BN affine: a = g*rsqrt(var+eps), c = be - a*mean -
__global__ void finalize_k(const float* __restrict__ gam, const float* __restrict__ bet) {
    int c = threadIdx.x;
    if (c < HID) {
        float mean = g_sum[c] * (1.0f / NNODES);
        float var = g_sumsq[c] * (1.0f / NNODES) - mean * mean;
        float rs = rsqrtf(var + BN_EPS);
        float a = gam[c] * rs;
        g_a[c] = a;
        g_c[c] = bet[c] - a * mean;
    }
}

// ---------------- final: relu(a*z+c) @ Wp2 + bp2, L2 normalize --------------
__global__ void __launch_bounds__(256) final_k(
    const float* __restrict__ Z, const float* __restrict__ W,
    const float* __restrict__ bias, float* __restrict__ out)
{
    __shared__ float Ws[HID * PROJ];   // 96*64 = 24KB
    __shared__ float zr[8][HID];

    int tid = threadIdx.x;
    for (int l = tid; l < HID * PROJ; l += 256) Ws[l] = W[l];
    __syncthreads();

    int warp = tid >> 5;
    int lane = tid & 31;

    for (int row = blockIdx.x * 8 + warp; row < NNODES; row += gridDim.x * 8) {
#pragma unroll
        for (int t = 0; t < 3; t++) {
            int k = lane + 32 * t;
            float v = Z[(long)row * HID + k];
            zr[warp][k] = fmaxf(fmaf(g_a[k], v, g_c[k]), 0.0f);
        }
        __syncwarp();

        float acc0 = bias[lane];
        float acc1 = bias[lane + 32];
#pragma unroll
        for (int k = 0; k < HID; k++) {
            float zv = zr[warp][k];
            acc0 = fmaf(zv, Ws[k * PROJ + lane], acc0);
            acc1 = fmaf(zv, Ws[k * PROJ + lane + 32], acc1);
        }

        float sq = acc0 * acc0 + acc1 * acc1;
#pragma unroll
        for (int o = 16; o; o >>= 1) sq += __shfl_xor_sync(0xffffffff, sq, o);
        float inv = 1.0f / fmaxf(sqrtf(sq), 1e-12f);

        out[(long)row * PROJ + lane] = acc0 * inv;
        out[(long)row * PROJ + lane + 32] = acc1 * inv;
        __syncwarp();
    }
}

// ---------------- host launch ----------------
extern "C" void kernel_launch(void* const* d_in, const int* in_sizes, int n_in,
                              void* d_out, int out_size) {
    const float* x   = (const float*)d_in[0];
    const void*  ei  = (const void*)d_in[1];
    const float* W1  = (const float*)d_in[2];
    const float* b1  = (const float*)d_in[3];
    const float* g1  = (const float*)d_in[4];
    const float* be1 = (const float*)d_in[5];
    const float* W2  = (const float*)d_in[6];
    const float* b2  = (const float*)d_in[7];
    const float* g2  = (const float*)d_in[8];
    const float* be2 = (const float*)d_in[9];
    const float* Wp1 = (const float*)d_in[10];
    const float* bp1 = (const float*)d_in[11];
    const float* gp  = (const float*)d_in[12];
    const float* bep = (const float*)d_in[13];
    const float* Wp2 = (const float*)d_in[14];
    const float* bp2 = (const float*)d_in[15];
    float* out = (float*)d_out;

    float *xws, *hbuf, *dinv, *acoef, *ccoef;
    cudaGetSymbolAddress((void**)&xws,   g_xws);
    cudaGetSymbolAddress((void**)&hbuf,  g_h);
    cudaGetSymbolAddress((void**)&dinv,  g_dinv);
    cudaGetSymbolAddress((void**)&acoef, g_a);
    cudaGetSymbolAddress((void**)&ccoef, g_c);

    const int gemm_grid   = (NNODES + BM - 1) / BM;           // 782
    const int node_grid   = (NNODES + 255) / 256;             // 196
    const int edge_grid   = (NEDGES + 255) / 256;             // 3125
    const int scat_grid   = (NEDGES + 31) / 32;               // 25000
    const long agg_total  = (long)NNODES * HID;
    const int zero_grid   = (int)((agg_total + 255) / 256);

    // dtype + degrees
    detect_dtype_k<<<1, 256>>>(ei);
    deg_init_k<<<node_grid, 256>>>();
    deg_scatter_k<<<edge_grid, 256>>>(ei);
    dinv_k<<<node_grid, 256>>>();

    // ---- GCN layer 1 ----
    gemm_k<<<gemm_grid, 256>>>(x, W1, nullptr, xws, NNODES, IN_DIM,
                               nullptr, nullptr, dinv);
    zero_agg_stats_k<<<zero_grid, 256>>>();
    scatter_k<<<scat_grid, 256>>>(ei);
    epilogue_k<<<1024, HID>>>(b1);
    finalize_k<<<1, HID>>>(g1, be1);

    // ---- GCN layer 2 (input transform = BN1 affine + relu) ----
    gemm_k<<<gemm_grid, 256>>>(hbuf, W2, nullptr, xws, NNODES, HID,
                               acoef, ccoef, dinv);
    zero_agg_stats_k<<<zero_grid, 256>>>();
    scatter_k<<<scat_grid, 256>>>(ei);
    epilogue_k<<<1024, HID>>>(b2);
    finalize_k<<<1, HID>>>(g2, be2);

    // ---- projector linear 1 (input transform = BN2 affine + relu) ----
    gemm_k<<<gemm_grid, 256>>>(hbuf, Wp1, bp1, xws, NNODES, HID,
                               acoef, ccoef, nullptr);
    zero_stats_k<<<1, HID>>>();
    stats_k<<<1024, HID>>>(xws);
    finalize_k<<<1, HID>>>(gp, bep);

    // ---- projector linear 2 + L2 normalize (transform = BN3 affine + relu)
    final_k<<<1024, 256>>>(xws, Wp2, bp2, out);
}

// round 3
// speedup vs baseline: 1.0492x; 1.0492x over previous
#include <cuda_runtime.h>
#include <cuda_bf16.h>
#include <math.h>

#define NNODES 50000
#define NEDGES 800000
#define IN_DIM 128
#define HID 96
#define PROJ 64
#define BN_EPS 1e-5f

// ---------------- scratch (device globals) ----------------
__device__ __align__(16) float g_xws[NNODES * HID];   // row-prescaled x@W
__device__ __align__(16) float g_h[NNODES * HID];     // pre-BN activations
__device__ float g_dinv[NNODES];
__device__ float g_sum[HID];
__device__ float g_sumsq[HID];
__device__ float g_a[HID];   // BN affine scale
__device__ float g_c[HID];   // BN affine shift
__device__ int   g_is64;     // edge_index dtype flag
__device__ int   g_cnt[NNODES];        // in-degree (w/o self loop)
__device__ int   g_rowptr[NNODES + 1];
__device__ int   g_cursor[NNODES];
__device__ int   g_csr[NEDGES];        // src node per edge, grouped by dst

// ---------------- dtype detection ----------------
__global__ void detect_dtype_k(const void* __restrict__ ei) {
    __shared__ int bad;
    if (threadIdx.x == 0) bad = 0;
    __syncthreads();
    const long long* p = (const long long*)ei;
    for (int i = threadIdx.x; i < 4096; i += blockDim.x) {
        long long v = p[i];
        if (v < 0 || v >= NNODES) bad = 1;
    }
    __syncthreads();
    if (threadIdx.x == 0) g_is64 = bad ? 0 : 1;
}

__device__ __forceinline__ int edge_at(const void* ei, long pos) {
    if (g_is64) return (int)((const long long*)ei)[pos];
    return ((const int*)ei)[pos];
}

// ---------------- CSR build ----------------
__global__ void zero_cnt_k() {
    int i = blockIdx.x * blockDim.x + threadIdx.x;
    if (i < NNODES) g_cnt[i] = 0;
}

__global__ void count_k(const void* __restrict__ ei) {
    int e = blockIdx.x * blockDim.x + threadIdx.x;
    if (e < NEDGES) atomicAdd(&g_cnt[edge_at(ei, (long)NEDGES + e)], 1);
}

__global__ void dinv_k() {
    int i = blockIdx.x * blockDim.x + threadIdx.x;
    if (i < NNODES) g_dinv[i] = rsqrtf((float)(g_cnt[i] + 1));  // + self loop
}

// single-block exclusive scan of g_cnt -> g_rowptr / g_cursor
__global__ void __launch_bounds__(1024) scan_k() {
    __shared__ int part[1024];
    int t = threadIdx.x;
    const int CH = (NNODES + 1023) / 1024;  // 49
    int st = t * CH, en = min(st + CH, NNODES);
    int sum = 0;
    for (int i = st; i < en; i++) sum += g_cnt[i];
    part[t] = sum;
    __syncthreads();
    // inclusive Hillis-Steele scan
    for (int off = 1; off < 1024; off <<= 1) {
        int v = (t >= off) ? part[t - off] : 0;
        __syncthreads();
        part[t] += v;
        __syncthreads();
    }
    int run = (t > 0) ? part[t - 1] : 0;
    for (int i = st; i < en; i++) {
        g_rowptr[i] = run;
        g_cursor[i] = run;
        run += g_cnt[i];
    }
    if (t == 1023) g_rowptr[NNODES] = part[1023];
}

__global__ void fill_k(const void* __restrict__ ei) {
    int e = blockIdx.x * blockDim.x + threadIdx.x;
    if (e < NEDGES) {
        int src = edge_at(ei, e);
        int dst = edge_at(ei, (long)NEDGES + e);
        int pos = atomicAdd(&g_cursor[dst], 1);
        g_csr[pos] = src;
    }
}

__global__ void zero_stats_k() {
    int i = threadIdx.x;
    if (i < HID) { g_sum[i] = 0.0f; g_sumsq[i] = 0.0f; }
}

// ---------------- GEMM: C[M,96] = f(A[M,K]) @ B[K,96] (+bias) (*rowscale) ---
// f(v) = relu(ta[k]*v + tc[k]) when ta != nullptr; optionally accumulates
// column stats (sum / sumsq) of the written C into g_sum/g_sumsq.
#define BM 64
#define BN 96
#define BK 32
__global__ void __launch_bounds__(256) gemm_k(
    const float* __restrict__ A, const float* __restrict__ B,
    const float* __restrict__ bias, float* __restrict__ C,
    int M, int K,
    const float* __restrict__ ta, const float* __restrict__ tc,
    const float* __restrict__ rowscale, int do_stats)
{
    __shared__ float As[BM][BK];
    __shared__ float Bs[BK][BN];
    __shared__ float ssum[BN], ssq[BN];

    int m0 = blockIdx.x * BM;
    int tid = threadIdx.x;
    int r = tid >> 4;      // 0..15
    int c = tid & 15;      // 0..15

    if (do_stats && tid < BN) { ssum[tid] = 0.0f; ssq[tid] = 0.0f; }

    float acc[4][6];
#pragma unroll
    for (int i = 0; i < 4; i++)
#pragma unroll
        for (int j = 0; j < 6; j++) acc[i][j] = 0.0f;

    for (int k0 = 0; k0 < K; k0 += BK) {
#pragma unroll
        for (int l = 0; l < 8; l++) {
            int idx = tid + l * 256;
            int mr = idx >> 5;
            int kc = idx & 31;
            int m = m0 + mr;
            int kk = k0 + kc;
            float v = 0.0f;
            if (m < M) {
                v = A[(long)m * K + kk];
                if (ta) v = fmaxf(fmaf(ta[kk], v, tc[kk]), 0.0f);
            }
            As[mr][kc] = v;
        }
#pragma unroll
        for (int l = 0; l < 12; l++) {
            int idx = tid + l * 256;
            int kr = idx / 96;
            int nc = idx % 96;
            Bs[kr][nc] = B[(long)(k0 + kr) * BN + nc];
        }
        __syncthreads();

#pragma unroll
        for (int k = 0; k < BK; k++) {
            float av[4], bv[6];
#pragma unroll
            for (int i = 0; i < 4; i++) av[i] = As[r + 16 * i][k];
#pragma unroll
            for (int j = 0; j < 6; j++) bv[j] = Bs[k][c + 16 * j];
#pragma unroll
            for (int i = 0; i < 4; i++)
#pragma unroll
                for (int j = 0; j < 6; j++)
                    acc[i][j] = fmaf(av[i], bv[j], acc[i][j]);
        }
        __syncthreads();
    }

#pragma unroll
    for (int i = 0; i < 4; i++) {
        int m = m0 + r + 16 * i;
        if (m < M) {
            float rs = rowscale ? rowscale[m] : 1.0f;
#pragma unroll
            for (int j = 0; j < 6; j++) {
                int n = c + 16 * j;
                float v = acc[i][j];
                if (bias) v += bias[n];
                v *= rs;
                C[(long)m * BN + n] = v;
                if (do_stats) {
                    atomicAdd(&ssum[n], v);
                    atomicAdd(&ssq[n], v * v);
                }
            }
        }
    }
    if (do_stats) {
        __syncthreads();
        if (tid < BN) {
            atomicAdd(&g_sum[tid], ssum[tid]);
            atomicAdd(&g_sumsq[tid], ssq[tid]);
        }
    }
}

// ------- fused aggregation + GCN epilogue + BN stats (warp per row) --------
// h[row] = dinv[row] * (sum_{s in N(row)} xws[s] + xws[row]) + bias
__global__ void __launch_bounds__(256) agg_k(const float* __restrict__ bias) {
    int gwarp = (blockIdx.x * blockDim.x + threadIdx.x) >> 5;
    int nwarps = (gridDim.x * blockDim.x) >> 5;
    int lane = threadIdx.x & 31;

    const float b0 = bias[lane];
    const float b1 = bias[lane + 32];
    const float b2 = bias[lane + 64];

    float s0 = 0.f, s1 = 0.f, s2 = 0.f;
    float q0 = 0.f, q1 = 0.f, q2 = 0.f;

    for (int row = gwarp; row < NNODES; row += nwarps) {
        int st = g_rowptr[row];
        int en = g_rowptr[row + 1];
        float a0 = 0.f, a1 = 0.f, a2 = 0.f;

        for (int base = st; base < en; base += 32) {
            int idx = base + lane;
            int s = (idx < en) ? g_csr[idx] : 0;
            int cnt = min(32, en - base);
#pragma unroll 4
            for (int j = 0; j < cnt; j++) {
                int sj = __shfl_sync(0xffffffff, s, j);
                const float* xr = g_xws + (long)sj * HID;
                a0 += xr[lane];
                a1 += xr[lane + 32];
                a2 += xr[lane + 64];
            }
        }
        float di = g_dinv[row];
        const float* xs = g_xws + (long)row * HID;
        float v0 = fmaf(di, a0 + xs[lane],      b0);
        float v1 = fmaf(di, a1 + xs[lane + 32], b1);
        float v2 = fmaf(di, a2 + xs[lane + 64], b2);
        float* hr = g_h + (long)row * HID;
        hr[lane]      = v0;
        hr[lane + 32] = v1;
        hr[lane + 64] = v2;
        s0 += v0; s1 += v1; s2 += v2;
        q0 += v0 * v0; q1 += v1 * v1; q2 += v2 * v2;
    }

    // block-level stats reduction
    __shared__ float red[2 * HID];
    if (threadIdx.x < 2 * HID) red[threadIdx.x] = 0.0f;
    __syncthreads();
    atomicAdd(&red[lane],            s0);
    atomicAdd(&red[lane + 32],       s1);
    atomicAdd(&red[lane + 64],       s2);
    atomicAdd(&red[HID + lane],      q0);
    atomicAdd(&red[HID + lane + 32], q1);
    atomicAdd(&red[HID + lane + 64], q2);
    __syncthreads();
    if (threadIdx.x < HID) {
        atomicAdd(&g_sum[threadIdx.x],   red[threadIdx.x]);
        atomicAdd(&g_sumsq[threadIdx.x], red[HID + threadIdx.x]);
    }
}

// ---------------- finalize BN affine ----------------
__global__ void finalize_k(const float* __restrict__ gam, const float* __restrict__ bet) {
    int c = threadIdx.x;
    if (c < HID) {
        float mean = g_sum[c] * (1.0f / NNODES);
        float var = g_sumsq[c] * (1.0f / NNODES) - mean * mean;
        float rs = rsqrtf(var + BN_EPS);
        float a = gam[c] * rs;
        g_a[c] = a;
        g_c[c] = bet[c] - a * mean;
    }
}

// ---------------- final: relu(a*z+c) @ Wp2 + bp2, L2 normalize --------------
__global__ void __launch_bounds__(256) final_k(
    const float* __restrict__ Z, const float* __restrict__ W,
    const float* __restrict__ bias, float* __restrict__ out)
{
    __shared__ float Ws[HID * PROJ];   // 24KB
    __shared__ float zr[8][HID];

    int tid = threadIdx.x;
    for (int l = tid; l < HID * PROJ; l += 256) Ws[l] = W[l];
    __syncthreads();

    int warp = tid >> 5;
    int lane = tid & 31;

    for (int row = blockIdx.x * 8 + warp; row < NNODES; row += gridDim.x * 8) {
#pragma unroll
        for (int t = 0; t < 3; t++) {
            int k = lane + 32 * t;
            float v = Z[(long)row * HID + k];
            zr[warp][k] = fmaxf(fmaf(g_a[k], v, g_c[k]), 0.0f);
        }
        __syncwarp();

        float acc0 = bias[lane];
        float acc1 = bias[lane + 32];
#pragma unroll
        for (int k = 0; k < HID; k++) {
            float zv = zr[warp][k];
            acc0 = fmaf(zv, Ws[k * PROJ + lane], acc0);
            acc1 = fmaf(zv, Ws[k * PROJ + lane + 32], acc1);
        }

        float sq = acc0 * acc0 + acc1 * acc1;
#pragma unroll
        for (int o = 16; o; o >>= 1) sq += __shfl_xor_sync(0xffffffff, sq, o);
        float inv = 1.0f / fmaxf(sqrtf(sq), 1e-12f);

        out[(long)row * PROJ + lane] = acc0 * inv;
        out[(long)row * PROJ + lane + 32] = acc1 * inv;
        __syncwarp();
    }
}

// ---------------- host launch ----------------
extern "C" void kernel_launch(void* const* d_in, const int* in_sizes, int n_in,
                              void* d_out, int out_size) {
    const float* x   = (const float*)d_in[0];
    const void*  ei  = (const void*)d_in[1];
    const float* W1  = (const float*)d_in[2];
    const float* b1  = (const float*)d_in[3];
    const float* g1  = (const float*)d_in[4];
    const float* be1 = (const float*)d_in[5];
    const float* W2  = (const float*)d_in[6];
    const float* b2  = (const float*)d_in[7];
    const float* g2  = (const float*)d_in[8];
    const float* be2 = (const float*)d_in[9];
    const float* Wp1 = (const float*)d_in[10];
    const float* bp1 = (const float*)d_in[11];
    const float* gp  = (const float*)d_in[12];
    const float* bep = (const float*)d_in[13];
    const float* Wp2 = (const float*)d_in[14];
    const float* bp2 = (const float*)d_in[15];
    float* out = (float*)d_out;

    float *xws, *hbuf, *dinv, *acoef, *ccoef;
    cudaGetSymbolAddress((void**)&xws,   g_xws);
    cudaGetSymbolAddress((void**)&hbuf,  g_h);
    cudaGetSymbolAddress((void**)&dinv,  g_dinv);
    cudaGetSymbolAddress((void**)&acoef, g_a);
    cudaGetSymbolAddress((void**)&ccoef, g_c);

    const int gemm_grid = (NNODES + BM - 1) / BM;   // 782
    const int node_grid = (NNODES + 255) / 256;     // 196
    const int edge_grid = (NEDGES + 255) / 256;     // 3125
    const int agg_grid  = 1184;

    // ---- CSR build (amortized over both GCN layers) ----
    detect_dtype_k<<<1, 256>>>(ei);
    zero_cnt_k<<<node_grid, 256>>>();
    count_k<<<edge_grid, 256>>>(ei);
    dinv_k<<<node_grid, 256>>>();
    scan_k<<<1, 1024>>>();
    fill_k<<<edge_grid, 256>>>(ei);

    // ---- GCN layer 1 ----
    gemm_k<<<gemm_grid, 256>>>(x, W1, nullptr, xws, NNODES, IN_DIM,
                               nullptr, nullptr, dinv, 0);
    zero_stats_k<<<1, HID>>>();
    agg_k<<<agg_grid, 256>>>(b1);
    finalize_k<<<1, HID>>>(g1, be1);

    // ---- GCN layer 2 ----
    gemm_k<<<gemm_grid, 256>>>(hbuf, W2, nullptr, xws, NNODES, HID,
                               acoef, ccoef, dinv, 0);
    zero_stats_k<<<1, HID>>>();
    agg_k<<<agg_grid, 256>>>(b2);
    finalize_k<<<1, HID>>>(g2, be2);

    // ---- projector linear 1 (stats fused into GEMM epilogue) ----
    zero_stats_k<<<1, HID>>>();
    gemm_k<<<gemm_grid, 256>>>(hbuf, Wp1, bp1, xws, NNODES, HID,
                               acoef, ccoef, nullptr, 1);
    finalize_k<<<1, HID>>>(gp, bep);

    // ---- projector linear 2 + L2 normalize ----
    final_k<<<1024, 256>>>(xws, Wp2, bp2, out);
}

// round 4
// speedup vs baseline: 1.0620x; 1.0122x over previous
#include <cuda_runtime.h>
#include <cuda_bf16.h>
#include <math.h>

#define NNODES 50000
#define NEDGES 800000
#define IN_DIM 128
#define HID 96
#define PROJ 64
#define BN_EPS 1e-5f

// ---------------- scratch (device globals) ----------------
__device__ __align__(16) float g_xws[NNODES * HID];   // row-prescaled x@W
__device__ __align__(16) float g_h[NNODES * HID];     // pre-BN activations
__device__ float g_dinv[NNODES];
__device__ float g_sum[HID];
__device__ float g_sumsq[HID];
__device__ float g_a[HID];   // BN affine scale
__device__ float g_c[HID];   // BN affine shift
__device__ int   g_is64;     // edge_index dtype flag
__device__ int   g_cnt[NNODES];
__device__ int   g_rowptr[NNODES + 1];
__device__ int   g_cursor[NNODES];
__device__ int   g_csr[NEDGES];

// ---------------- dtype detection ----------------
__global__ void detect_dtype_k(const void* __restrict__ ei) {
    __shared__ int bad;
    if (threadIdx.x == 0) bad = 0;
    __syncthreads();
    const long long* p = (const long long*)ei;
    for (int i = threadIdx.x; i < 4096; i += blockDim.x) {
        long long v = p[i];
        if (v < 0 || v >= NNODES) bad = 1;
    }
    __syncthreads();
    if (threadIdx.x == 0) g_is64 = bad ? 0 : 1;
}

__device__ __forceinline__ int edge_at(const void* ei, long pos) {
    if (g_is64) return (int)((const long long*)ei)[pos];
    return ((const int*)ei)[pos];
}

// ---------------- CSR build ----------------
__global__ void zero_cnt_k() {
    int i = blockIdx.x * blockDim.x + threadIdx.x;
    if (i < NNODES) g_cnt[i] = 0;
}

__global__ void count_k(const void* __restrict__ ei) {
    int e = blockIdx.x * blockDim.x + threadIdx.x;
    if (e < NEDGES) atomicAdd(&g_cnt[edge_at(ei, (long)NEDGES + e)], 1);
}

__global__ void dinv_k() {
    int i = blockIdx.x * blockDim.x + threadIdx.x;
    if (i < NNODES) g_dinv[i] = rsqrtf((float)(g_cnt[i] + 1));
}

__global__ void __launch_bounds__(1024) scan_k() {
    __shared__ int part[1024];
    int t = threadIdx.x;
    const int CH = (NNODES + 1023) / 1024;
    int st = t * CH, en = min(st + CH, NNODES);
    int sum = 0;
    for (int i = st; i < en; i++) sum += g_cnt[i];
    part[t] = sum;
    __syncthreads();
    for (int off = 1; off < 1024; off <<= 1) {
        int v = (t >= off) ? part[t - off] : 0;
        __syncthreads();
        part[t] += v;
        __syncthreads();
    }
    int run = (t > 0) ? part[t - 1] : 0;
    for (int i = st; i < en; i++) {
        g_rowptr[i] = run;
        g_cursor[i] = run;
        run += g_cnt[i];
    }
    if (t == 1023) g_rowptr[NNODES] = part[1023];
}

__global__ void fill_k(const void* __restrict__ ei) {
    int e = blockIdx.x * blockDim.x + threadIdx.x;
    if (e < NEDGES) {
        int src = edge_at(ei, e);
        int dst = edge_at(ei, (long)NEDGES + e);
        int pos = atomicAdd(&g_cursor[dst], 1);
        g_csr[pos] = src;
    }
}

__global__ void zero_stats_k() {
    int i = threadIdx.x;
    if (i < HID) { g_sum[i] = 0.0f; g_sumsq[i] = 0.0f; }
}

// ---------------- 3xTF32 tensor-core GEMM ----------------
// C[M,96] = f(A[M,K]) @ B[K,96] (+bias) (*rowscale[row])
// f(v) = relu(ta[k]*v + tc[k]) when ta != nullptr
#define GBM 128
#define GBN 96
#define GBK 32
#define AS_STRIDE 36    // bank-conflict-free for A frag loads
#define BS_STRIDE 104   // bank-conflict-free for B frag loads

__device__ __forceinline__ unsigned f2tf(float x) {
    unsigned r;
    asm("cvt.rna.tf32.f32 %0, %1;" : "=r"(r) : "f"(x));
    return r;
}

#define MMA_TF32(d, a0, a1, a2, a3, b0, b1)                                   \
    asm volatile(                                                             \
        "mma.sync.aligned.m16n8k8.row.col.f32.tf32.tf32.f32 "                 \
        "{%0,%1,%2,%3},{%4,%5,%6,%7},{%8,%9},{%0,%1,%2,%3};"                  \
        : "+f"(d[0]), "+f"(d[1]), "+f"(d[2]), "+f"(d[3])                      \
        : "r"(a0), "r"(a1), "r"(a2), "r"(a3), "r"(b0), "r"(b1))

__global__ void __launch_bounds__(256) tgemm_k(
    const float* __restrict__ A, const float* __restrict__ B,
    const float* __restrict__ bias, float* __restrict__ C,
    int M, int K,
    const float* __restrict__ ta, const float* __restrict__ tc,
    const float* __restrict__ rowscale)
{
    __shared__ float As[GBM * AS_STRIDE];   // 18.4KB
    __shared__ float Bs[GBK * BS_STRIDE];   // 13.3KB

    int m0 = blockIdx.x * GBM;
    int tid = threadIdx.x;
    int wid = tid >> 5, lane = tid & 31;
    int g = lane >> 2, t4 = lane & 3;
    int wrow = wid >> 1;         // 0..3
    int wcol = wid & 1;          // 0..1
    int rbase = wrow * 32;
    int cbase = wcol * 48;

    float acc[12][4];
#pragma unroll
    for (int t = 0; t < 12; t++)
#pragma unroll
        for (int q = 0; q < 4; q++) acc[t][q] = 0.0f;

    for (int k0 = 0; k0 < K; k0 += GBK) {
        // stage A tile 128x32 with optional BN+ReLU transform
#pragma unroll
        for (int l = 0; l < 16; l++) {
            int idx = l * 256 + tid;
            int row = idx >> 5;
            int col = idx & 31;
            int m = m0 + row;
            int kk = k0 + col;
            float v = 0.0f;
            if (m < M) {
                v = A[(long)m * K + kk];
                if (ta) v = fmaxf(fmaf(ta[kk], v, tc[kk]), 0.0f);
            }
            As[row * AS_STRIDE + col] = v;
        }
        // stage B tile 32x96
#pragma unroll
        for (int l = 0; l < 12; l++) {
            int idx = l * 256 + tid;
            int kr = idx / 96;
            int nc = idx - kr * 96;
            Bs[kr * BS_STRIDE + nc] = B[(long)(k0 + kr) * GBN + nc];
        }
        __syncthreads();

#pragma unroll
        for (int kk = 0; kk < GBK; kk += 8) {
            unsigned ahi[2][4], alo[2][4];
#pragma unroll
            for (int i = 0; i < 2; i++) {
                int r0 = (rbase + i * 16 + g) * AS_STRIDE;
                int r1 = (rbase + i * 16 + 8 + g) * AS_STRIDE;
                float v0 = As[r0 + kk + t4];
                float v1 = As[r1 + kk + t4];
                float v2 = As[r0 + kk + 4 + t4];
                float v3 = As[r1 + kk + 4 + t4];
                ahi[i][0] = f2tf(v0); alo[i][0] = f2tf(v0 - __uint_as_float(ahi[i][0]));
                ahi[i][1] = f2tf(v1); alo[i][1] = f2tf(v1 - __uint_as_float(ahi[i][1]));
                ahi[i][2] = f2tf(v2); alo[i][2] = f2tf(v2 - __uint_as_float(ahi[i][2]));
                ahi[i][3] = f2tf(v3); alo[i][3] = f2tf(v3 - __uint_as_float(ahi[i][3]));
            }
            unsigned bhi[6][2], blo[6][2];
#pragma unroll
            for (int j = 0; j < 6; j++) {
                int n = cbase + j * 8 + g;
                float u0 = Bs[(kk + t4) * BS_STRIDE + n];
                float u1 = Bs[(kk + 4 + t4) * BS_STRIDE + n];
                bhi[j][0] = f2tf(u0); blo[j][0] = f2tf(u0 - __uint_as_float(bhi[j][0]));
                bhi[j][1] = f2tf(u1); blo[j][1] = f2tf(u1 - __uint_as_float(bhi[j][1]));
            }
#pragma unroll
            for (int i = 0; i < 2; i++)
#pragma unroll
                for (int j = 0; j < 6; j++) {
                    float* d = acc[i * 6 + j];
                    MMA_TF32(d, ahi[i][0], ahi[i][1], ahi[i][2], ahi[i][3],
                             blo[j][0], blo[j][1]);
                    MMA_TF32(d, alo[i][0], alo[i][1], alo[i][2], alo[i][3],
                             bhi[j][0], bhi[j][1]);
                    MMA_TF32(d, ahi[i][0], ahi[i][1], ahi[i][2], ahi[i][3],
                             bhi[j][0], bhi[j][1]);
                }
        }
        __syncthreads();
    }

    // epilogue
#pragma unroll
    for (int i = 0; i < 2; i++) {
#pragma unroll
        for (int h = 0; h < 2; h++) {
            int row = m0 + rbase + i * 16 + g + h * 8;
            if (row < M) {
                float rs = rowscale ? rowscale[row] : 1.0f;
#pragma unroll
                for (int j = 0; j < 6; j++) {
                    int col = cbase + j * 8 + t4 * 2;
                    float v0 = acc[i * 6 + j][h * 2 + 0];
                    float v1 = acc[i * 6 + j][h * 2 + 1];
                    if (bias) { v0 += bias[col]; v1 += bias[col + 1]; }
                    v0 *= rs; v1 *= rs;
                    float2 o; o.x = v0; o.y = v1;
                    *(float2*)(C + (long)row * GBN + col) = o;
                }
            }
        }
    }
}

// ------- fused aggregation + GCN epilogue + BN stats (warp per row) --------
__global__ void __launch_bounds__(256) agg_k(const float* __restrict__ bias) {
    int gwarp = (blockIdx.x * blockDim.x + threadIdx.x) >> 5;
    int nwarps = (gridDim.x * blockDim.x) >> 5;
    int lane = threadIdx.x & 31;

    const float b0 = bias[lane];
    const float b1 = bias[lane + 32];
    const float b2 = bias[lane + 64];

    float s0 = 0.f, s1 = 0.f, s2 = 0.f;
    float q0 = 0.f, q1 = 0.f, q2 = 0.f;

    for (int row = gwarp; row < NNODES; row += nwarps) {
        int st = g_rowptr[row];
        int en = g_rowptr[row + 1];
        float a0 = 0.f, a1 = 0.f, a2 = 0.f;

        for (int base = st; base < en; base += 32) {
            int idx = base + lane;
            int s = (idx < en) ? g_csr[idx] : 0;
            int cnt = min(32, en - base);
#pragma unroll 4
            for (int j = 0; j < cnt; j++) {
                int sj = __shfl_sync(0xffffffff, s, j);
                const float* xr = g_xws + (long)sj * HID;
                a0 += xr[lane];
                a1 += xr[lane + 32];
                a2 += xr[lane + 64];
            }
        }
        float di = g_dinv[row];
        const float* xs = g_xws + (long)row * HID;
        float v0 = fmaf(di, a0 + xs[lane],      b0);
        float v1 = fmaf(di, a1 + xs[lane + 32], b1);
        float v2 = fmaf(di, a2 + xs[lane + 64], b2);
        float* hr = g_h + (long)row * HID;
        hr[lane]      = v0;
        hr[lane + 32] = v1;
        hr[lane + 64] = v2;
        s0 += v0; s1 += v1; s2 += v2;
        q0 += v0 * v0; q1 += v1 * v1; q2 += v2 * v2;
    }

    __shared__ float red[2 * HID];
    if (threadIdx.x < 2 * HID) red[threadIdx.x] = 0.0f;
    __syncthreads();
    atomicAdd(&red[lane],            s0);
    atomicAdd(&red[lane + 32],       s1);
    atomicAdd(&red[lane + 64],       s2);
    atomicAdd(&red[HID + lane],      q0);
    atomicAdd(&red[HID + lane + 32], q1);
    atomicAdd(&red[HID + lane + 64], q2);
    __syncthreads();
    if (threadIdx.x < HID) {
        atomicAdd(&g_sum[threadIdx.x],   red[threadIdx.x]);
        atomicAdd(&g_sumsq[threadIdx.x], red[HID + threadIdx.x]);
    }
}

// ---------------- column stats of a [N,96] matrix ----------------
__global__ void stats_k(const float* __restrict__ X) {
    int c = threadIdx.x;
    int rows_per = (NNODES + gridDim.x - 1) / gridDim.x;
    int r0 = blockIdx.x * rows_per;
    int r1 = min(r0 + rows_per, NNODES);
    float s = 0.0f, ss = 0.0f;
    for (int r = r0; r < r1; r++) {
        float v = X[(long)r * HID + c];
        s += v;
        ss += v * v;
    }
    atomicAdd(&g_sum[c], s);
    atomicAdd(&g_sumsq[c], ss);
}

// ---------------- finalize BN affine ----------------
__global__ void finalize_k(const float* __restrict__ gam, const float* __restrict__ bet) {
    int c = threadIdx.x;
    if (c < HID) {
        float mean = g_sum[c] * (1.0f / NNODES);
        float var = g_sumsq[c] * (1.0f / NNODES) - mean * mean;
        float rs = rsqrtf(var + BN_EPS);
        float a = gam[c] * rs;
        g_a[c] = a;
        g_c[c] = bet[c] - a * mean;
    }
}

// ---------------- final: relu(a*z+c) @ Wp2 + bp2, L2 normalize --------------
__global__ void __launch_bounds__(256) final_k(
    const float* __restrict__ Z, const float* __restrict__ W,
    const float* __restrict__ bias, float* __restrict__ out)
{
    __shared__ float Ws[HID * PROJ];
    __shared__ float zr[8][HID];

    int tid = threadIdx.x;
    for (int l = tid; l < HID * PROJ; l += 256) Ws[l] = W[l];
    __syncthreads();

    int warp = tid >> 5;
    int lane = tid & 31;

    for (int row = blockIdx.x * 8 + warp; row < NNODES; row += gridDim.x * 8) {
#pragma unroll
        for (int t = 0; t < 3; t++) {
            int k = lane + 32 * t;
            float v = Z[(long)row * HID + k];
            zr[warp][k] = fmaxf(fmaf(g_a[k], v, g_c[k]), 0.0f);
        }
        __syncwarp();

        float acc0 = bias[lane];
        float acc1 = bias[lane + 32];
#pragma unroll
        for (int k = 0; k < HID; k++) {
            float zv = zr[warp][k];
            acc0 = fmaf(zv, Ws[k * PROJ + lane], acc0);
            acc1 = fmaf(zv, Ws[k * PROJ + lane + 32], acc1);
        }

        float sq = acc0 * acc0 + acc1 * acc1;
#pragma unroll
        for (int o = 16; o; o >>= 1) sq += __shfl_xor_sync(0xffffffff, sq, o);
        float inv = 1.0f / fmaxf(sqrtf(sq), 1e-12f);

        out[(long)row * PROJ + lane] = acc0 * inv;
        out[(long)row * PROJ + lane + 32] = acc1 * inv;
        __syncwarp();
    }
}

// ---------------- host launch ----------------
extern "C" void kernel_launch(void* const* d_in, const int* in_sizes, int n_in,
                              void* d_out, int out_size) {
    const float* x   = (const float*)d_in[0];
    const void*  ei  = (const void*)d_in[1];
    const float* W1  = (const float*)d_in[2];
    const float* b1  = (const float*)d_in[3];
    const float* g1  = (const float*)d_in[4];
    const float* be1 = (const float*)d_in[5];
    const float* W2  = (const float*)d_in[6];
    const float* b2  = (const float*)d_in[7];
    const float* g2  = (const float*)d_in[8];
    const float* be2 = (const float*)d_in[9];
    const float* Wp1 = (const float*)d_in[10];
    const float* bp1 = (const float*)d_in[11];
    const float* gp  = (const float*)d_in[12];
    const float* bep = (const float*)d_in[13];
    const float* Wp2 = (const float*)d_in[14];
    const float* bp2 = (const float*)d_in[15];
    float* out = (float*)d_out;

    float *xws, *hbuf, *dinv, *acoef, *ccoef;
    cudaGetSymbolAddress((void**)&xws,   g_xws);
    cudaGetSymbolAddress((void**)&hbuf,  g_h);
    cudaGetSymbolAddress((void**)&dinv,  g_dinv);
    cudaGetSymbolAddress((void**)&acoef, g_a);
    cudaGetSymbolAddress((void**)&ccoef, g_c);

    const int gemm_grid = (NNODES + GBM - 1) / GBM;   // 391
    const int node_grid = (NNODES + 255) / 256;
    const int edge_grid = (NEDGES + 255) / 256;
    const int agg_grid  = 1184;

    // ---- CSR build ----
    detect_dtype_k<<<1, 256>>>(ei);
    zero_cnt_k<<<node_grid, 256>>>();
    count_k<<<edge_grid, 256>>>(ei);
    dinv_k<<<node_grid, 256>>>();
    scan_k<<<1, 1024>>>();
    fill_k<<<edge_grid, 256>>>(ei);

    // ---- GCN layer 1 ----
    tgemm_k<<<gemm_grid, 256>>>(x, W1, nullptr, xws, NNODES, IN_DIM,
                                nullptr, nullptr, dinv);
    zero_stats_k<<<1, HID>>>();
    agg_k<<<agg_grid, 256>>>(b1);
    finalize_k<<<1, HID>>>(g1, be1);

    // ---- GCN layer 2 ----
    tgemm_k<<<gemm_grid, 256>>>(hbuf, W2, nullptr, xws, NNODES, HID,
                                acoef, ccoef, dinv);
    zero_stats_k<<<1, HID>>>();
    agg_k<<<agg_grid, 256>>>(b2);
    finalize_k<<<1, HID>>>(g2, be2);

    // ---- projector linear 1 ----
    tgemm_k<<<gemm_grid, 256>>>(hbuf, Wp1, bp1, xws, NNODES, HID,
                                acoef, ccoef, nullptr);
    zero_stats_k<<<1, HID>>>();
    stats_k<<<1024, HID>>>(xws);
    finalize_k<<<1, HID>>>(gp, bep);

    // ---- projector linear 2 + L2 normalize ----
    final_k<<<1024, 256>>>(xws, Wp2, bp2, out);
}